// round 4
// baseline (speedup 1.0000x reference)
#include <cuda_runtime.h>

#define NB   64
#define CIMG 2048
#define HW   256
#define CO   1024
#define LTXT 64
#define CTXT 1024

// ---- scratch (static device arrays; no runtime allocation) ----
__device__ float g_img_embed[(size_t)NB * CO * HW];    // [n][1024][256]  64 MB
__device__ float g_img_cat [(size_t)NB * CO * LTXT];   // [n][1024][64]   16 MB
__device__ float g_gamma   [(size_t)NB * CO * LTXT];   // 16 MB
__device__ float g_beta    [(size_t)NB * CO * LTXT];   // 16 MB

// ============================================================================
// K1: img_embed[n][o][s] = sum_c w[o][c] * img[n][c][s]
// per-batch GEMM M=1024 N=256 K=2048; tile 128x128, BK=8, 256 thr, 8x8 frag.
// Double-buffered smem: one barrier per K-step, loads overlapped with FMAs.
// ============================================================================
__global__ __launch_bounds__(256) void k1_img_embed(
        const float* __restrict__ img, const float* __restrict__ w) {
    __shared__ float As[2][8][128];
    __shared__ float Bs[2][8][128];
    const int n  = blockIdx.z;
    const int o0 = blockIdx.y * 128;
    const int s0 = blockIdx.x * 128;
    const float* B = img + (size_t)n * CIMG * HW;
    float* C = g_img_embed + (size_t)n * CO * HW;
    const int tid = threadIdx.x;
    const int tx = tid & 15, ty = tid >> 4;

    float acc[8][8];
#pragma unroll
    for (int i = 0; i < 8; i++)
#pragma unroll
        for (int j = 0; j < 8; j++) acc[i][j] = 0.f;

    const int amm = tid >> 1;          // 0..127  (o row within tile)
    const int akk = (tid & 1) * 4;     // 0 or 4
    const int bkk = tid >> 5;          // 0..7
    const int bss = (tid & 31) * 4;    // 0..124
    const float* aptr = w + (size_t)(o0 + amm) * CIMG + akk;
    const float* bptr = B + (size_t)bkk * HW + s0 + bss;

    // prologue: fill buffer 0
    {
        float4 av = *(const float4*)(aptr);
        As[0][akk + 0][amm] = av.x; As[0][akk + 1][amm] = av.y;
        As[0][akk + 2][amm] = av.z; As[0][akk + 3][amm] = av.w;
        *(float4*)&Bs[0][bkk][bss] = *(const float4*)(bptr);
    }
    __syncthreads();

    int buf = 0;
    for (int k0 = 0; k0 < CIMG; k0 += 8) {
        const bool has_next = (k0 + 8) < CIMG;
        float4 nav, nbv;
        if (has_next) {
            nav = *(const float4*)(aptr + k0 + 8);
            nbv = *(const float4*)(bptr + (size_t)(k0 + 8) * HW);
        }
#pragma unroll
        for (int kk = 0; kk < 8; kk++) {
            float4 a0 = *(const float4*)&As[buf][kk][ty * 4];
            float4 a1 = *(const float4*)&As[buf][kk][64 + ty * 4];
            float4 b0 = *(const float4*)&Bs[buf][kk][tx * 4];
            float4 b1 = *(const float4*)&Bs[buf][kk][64 + tx * 4];
            float a[8] = {a0.x, a0.y, a0.z, a0.w, a1.x, a1.y, a1.z, a1.w};
            float b[8] = {b0.x, b0.y, b0.z, b0.w, b1.x, b1.y, b1.z, b1.w};
#pragma unroll
            for (int i = 0; i < 8; i++)
#pragma unroll
                for (int j = 0; j < 8; j++)
                    acc[i][j] = fmaf(a[i], b[j], acc[i][j]);
        }
        if (has_next) {
            const int nb = buf ^ 1;
            As[nb][akk + 0][amm] = nav.x; As[nb][akk + 1][amm] = nav.y;
            As[nb][akk + 2][amm] = nav.z; As[nb][akk + 3][amm] = nav.w;
            *(float4*)&Bs[nb][bkk][bss] = nbv;
            __syncthreads();
            buf = nb;
        }
    }
#pragma unroll
    for (int ih = 0; ih < 2; ih++)
#pragma unroll
        for (int i = 0; i < 4; i++) {
            const int o = o0 + ih * 64 + ty * 4 + i;
#pragma unroll
            for (int jh = 0; jh < 2; jh++) {
                const int s = s0 + jh * 64 + tx * 4;
                float4 v = make_float4(acc[ih*4+i][jh*4+0], acc[ih*4+i][jh*4+1],
                                       acc[ih*4+i][jh*4+2], acc[ih*4+i][jh*4+3]);
                *(float4*)&C[(size_t)o * HW + s] = v;
            }
        }
}

// ============================================================================
// K2: logits[n][l][s] = 0.25 * sum_c text[n][l][c] * img_embed[n][c][s]
// M=64 N=256 K=1024; tile 64x64, BK=16, 256 thr, 4x4 frag. Writes into attn out.
// ============================================================================
__global__ __launch_bounds__(256) void k2_logits(
        const float* __restrict__ text, float* __restrict__ attn) {
    __shared__ float As[16][64];  // [k][l]
    __shared__ float Bs[16][64];  // [k][s]
    const int n  = blockIdx.y;
    const int s0 = blockIdx.x * 64;
    const float* A = text + (size_t)n * LTXT * CTXT;
    const float* B = g_img_embed + (size_t)n * CO * HW;
    float* C = attn + (size_t)n * LTXT * HW;
    const int tid = threadIdx.x;
    const int tx = tid & 15, ty = tid >> 4;

    float acc[4][4];
#pragma unroll
    for (int i = 0; i < 4; i++)
#pragma unroll
        for (int j = 0; j < 4; j++) acc[i][j] = 0.f;

    const int all = tid >> 2;          // 0..63
    const int akk = (tid & 3) * 4;     // 0..12
    const int bkk = tid >> 4;          // 0..15
    const int bss = (tid & 15) * 4;

    for (int k0 = 0; k0 < CTXT; k0 += 16) {
        float4 av = *(const float4*)&A[(size_t)all * CTXT + k0 + akk];
        As[akk + 0][all] = av.x; As[akk + 1][all] = av.y;
        As[akk + 2][all] = av.z; As[akk + 3][all] = av.w;
        *(float4*)&Bs[bkk][bss] =
            *(const float4*)&B[(size_t)(k0 + bkk) * HW + s0 + bss];
        __syncthreads();
#pragma unroll
        for (int kk = 0; kk < 16; kk++) {
            float a[4], b[4];
#pragma unroll
            for (int i = 0; i < 4; i++) a[i] = As[kk][ty * 4 + i];
#pragma unroll
            for (int j = 0; j < 4; j++) b[j] = Bs[kk][tx * 4 + j];
#pragma unroll
            for (int i = 0; i < 4; i++)
#pragma unroll
                for (int j = 0; j < 4; j++)
                    acc[i][j] = fmaf(a[i], b[j], acc[i][j]);
        }
        __syncthreads();
    }
#pragma unroll
    for (int i = 0; i < 4; i++) {
        const int l = ty * 4 + i;
        float4 v = make_float4(acc[i][0] * 0.25f, acc[i][1] * 0.25f,
                               acc[i][2] * 0.25f, acc[i][3] * 0.25f);
        *(float4*)&C[(size_t)l * HW + s0 + tx * 4] = v;
    }
}

// ============================================================================
// K3: in-place softmax over s=256 per (n,l) row
// ============================================================================
__global__ __launch_bounds__(256) void k3_softmax(float* __restrict__ attn) {
    float* p = attn + (size_t)blockIdx.x * HW;
    const int t = threadIdx.x;
    __shared__ float red[256];
    float v = p[t];
    red[t] = v;
    __syncthreads();
#pragma unroll
    for (int s = 128; s > 0; s >>= 1) {
        if (t < s) red[t] = fmaxf(red[t], red[t + s]);
        __syncthreads();
    }
    const float m = red[0];
    __syncthreads();
    float e = __expf(v - m);
    red[t] = e;
    __syncthreads();
#pragma unroll
    for (int s = 128; s > 0; s >>= 1) {
        if (t < s) red[t] += red[t + s];
        __syncthreads();
    }
    p[t] = e * (1.0f / red[0]);
}

// ============================================================================
// K4: img_cat[n][c][l] = sum_s img_embed[n][c][s] * attn[n][l][s]
// M=1024 N=64 K=256; NT gemm, tile 64x64, BK=16, 4x4 frag, padded smem
// ============================================================================
__global__ __launch_bounds__(256) void k4_img_cat(const float* __restrict__ attn) {
    __shared__ float As[64][17];  // [c][k]
    __shared__ float Bs[64][17];  // [l][k]
    const int n  = blockIdx.y;
    const int c0 = blockIdx.x * 64;
    const float* A = g_img_embed + (size_t)n * CO * HW;
    const float* B = attn + (size_t)n * LTXT * HW;
    float* C = g_img_cat + (size_t)n * CO * LTXT;
    const int tid = threadIdx.x;
    const int tx = tid & 15, ty = tid >> 4;

    float acc[4][4];
#pragma unroll
    for (int i = 0; i < 4; i++)
#pragma unroll
        for (int j = 0; j < 4; j++) acc[i][j] = 0.f;

    const int mm  = tid >> 2;         // 0..63
    const int kkb = (tid & 3) * 4;

    for (int k0 = 0; k0 < HW; k0 += 16) {
        float4 av = *(const float4*)&A[(size_t)(c0 + mm) * HW + k0 + kkb];
        As[mm][kkb + 0] = av.x; As[mm][kkb + 1] = av.y;
        As[mm][kkb + 2] = av.z; As[mm][kkb + 3] = av.w;
        float4 bv = *(const float4*)&B[(size_t)mm * HW + k0 + kkb];
        Bs[mm][kkb + 0] = bv.x; Bs[mm][kkb + 1] = bv.y;
        Bs[mm][kkb + 2] = bv.z; Bs[mm][kkb + 3] = bv.w;
        __syncthreads();
#pragma unroll
        for (int kk = 0; kk < 16; kk++) {
            float a[4], b[4];
#pragma unroll
            for (int i = 0; i < 4; i++) a[i] = As[ty * 4 + i][kk];
#pragma unroll
            for (int j = 0; j < 4; j++) b[j] = Bs[tx * 4 + j][kk];
#pragma unroll
            for (int i = 0; i < 4; i++)
#pragma unroll
                for (int j = 0; j < 4; j++)
                    acc[i][j] = fmaf(a[i], b[j], acc[i][j]);
        }
        __syncthreads();
    }
#pragma unroll
    for (int i = 0; i < 4; i++) {
        const int c = c0 + ty * 4 + i;
        float4 v = make_float4(acc[i][0], acc[i][1], acc[i][2], acc[i][3]);
        *(float4*)&C[(size_t)c * LTXT + tx * 4] = v;
    }
}

// ---- X-tile loaders for the inception kernels ----
// Xs[kk][l] = x[n][ci0+kk][l]; x = concat(text^T, img_cat) over channels
__device__ __forceinline__ void load_x_frag(
        float4 xv[2], const float* __restrict__ T,
        const float* __restrict__ IC, int k0, int tid) {
    if (k0 < CTXT) {  // text half: text[n][l][c], c contiguous
#pragma unroll
        for (int it = 0; it < 2; it++) {
            const int l   = (tid >> 2) + it * 32;   // 0..63
            const int kkb = (tid & 3) * 4;
            xv[it] = *(const float4*)&T[(size_t)l * CTXT + k0 + kkb];
        }
    } else {          // img_cat half: [c][l], l contiguous
#pragma unroll
        for (int it = 0; it < 2; it++) {
            const int kk = (tid >> 4) + it * 8;     // 0..15
            const int lb = (tid & 15) * 4;
            xv[it] = *(const float4*)&IC[(size_t)(k0 - CTXT + kk) * LTXT + lb];
        }
    }
}

__device__ __forceinline__ void store_x_frag(
        float Xs[16][64], const float4 xv[2], int k0, int tid) {
    if (k0 < CTXT) {
#pragma unroll
        for (int it = 0; it < 2; it++) {
            const int l   = (tid >> 2) + it * 32;
            const int kkb = (tid & 3) * 4;
            Xs[kkb + 0][l] = xv[it].x; Xs[kkb + 1][l] = xv[it].y;
            Xs[kkb + 2][l] = xv[it].z; Xs[kkb + 3][l] = xv[it].w;
        }
    } else {
#pragma unroll
        for (int it = 0; it < 2; it++) {
            const int kk = (tid >> 4) + it * 8;
            const int lb = (tid & 15) * 4;
            *(float4*)&Xs[kk][lb] = xv[it];
        }
    }
}

__device__ __forceinline__ void load_x_tile(
        float Xs[16][64], const float* __restrict__ T,
        const float* __restrict__ IC, int k0, int tid) {
    float4 xv[2];
    load_x_frag(xv, T, IC, k0, tid);
    store_x_frag(Xs, xv, k0, tid);
}

// ============================================================================
// K5a: k=1 inception branch. out channels [0,512). GEMM M=512 N=64 K=2048.
// tile 128x64, BK=16, 128 thr (tx 0..7, ty 0..15), 8x8 frag.
// Double-buffered smem (register prefetch, one barrier per K-step).
// blockIdx.z: 0 -> gamma (wg), 1 -> beta (wb)
// ============================================================================
__global__ __launch_bounds__(128) void k5_conv1(
        const float* __restrict__ text,
        const float* __restrict__ wg, const float* __restrict__ bg,
        const float* __restrict__ wb, const float* __restrict__ bb) {
    __shared__ float Ws[2][16][128];
    __shared__ float Xs[2][16][64];
    const int n     = blockIdx.y;
    const int co0   = blockIdx.x * 128;   // 0..384
    const int which = blockIdx.z;
    const float* w1 = which ? wb : wg;
    const float* b1 = which ? bb : bg;
    const float* T  = text + (size_t)n * LTXT * CTXT;
    const float* IC = g_img_cat + (size_t)n * CO * LTXT;
    float* Cg = (which ? g_beta : g_gamma) + (size_t)n * CO * LTXT;
    const int tid = threadIdx.x;
    const int tx = tid & 7, ty = tid >> 3;

    float acc[8][8];
#pragma unroll
    for (int i = 0; i < 8; i++)
#pragma unroll
        for (int j = 0; j < 8; j++) acc[i][j] = 0.f;

    const int wmm  = tid >> 2;         // 0..31 (+32*it)
    const int wkkb = (tid & 3) * 4;
    const float* wptr = w1 + (size_t)(co0 + wmm) * CIMG + wkkb;

    // prologue: fill buffer 0
    {
#pragma unroll
        for (int it = 0; it < 4; it++) {
            float4 wv = *(const float4*)(wptr + (size_t)it * 32 * CIMG);
            const int mm = wmm + it * 32;
            Ws[0][wkkb + 0][mm] = wv.x; Ws[0][wkkb + 1][mm] = wv.y;
            Ws[0][wkkb + 2][mm] = wv.z; Ws[0][wkkb + 3][mm] = wv.w;
        }
        load_x_tile(Xs[0], T, IC, 0, tid);
    }
    __syncthreads();

    int buf = 0;
    for (int k0 = 0; k0 < CIMG; k0 += 16) {
        const bool has_next = (k0 + 16) < CIMG;
        float4 nwv[4], nxv[2];
        if (has_next) {
#pragma unroll
            for (int it = 0; it < 4; it++)
                nwv[it] = *(const float4*)(wptr + (size_t)it * 32 * CIMG + k0 + 16);
            load_x_frag(nxv, T, IC, k0 + 16, tid);
        }
#pragma unroll
        for (int kk = 0; kk < 16; kk++) {
            float4 a0 = *(const float4*)&Ws[buf][kk][ty * 4];
            float4 a1 = *(const float4*)&Ws[buf][kk][64 + ty * 4];
            float4 b0 = *(const float4*)&Xs[buf][kk][tx * 4];
            float4 b1 = *(const float4*)&Xs[buf][kk][32 + tx * 4];
            float a[8] = {a0.x, a0.y, a0.z, a0.w, a1.x, a1.y, a1.z, a1.w};
            float b[8] = {b0.x, b0.y, b0.z, b0.w, b1.x, b1.y, b1.z, b1.w};
#pragma unroll
            for (int i = 0; i < 8; i++)
#pragma unroll
                for (int j = 0; j < 8; j++)
                    acc[i][j] = fmaf(a[i], b[j], acc[i][j]);
        }
        if (has_next) {
            const int nb = buf ^ 1;
#pragma unroll
            for (int it = 0; it < 4; it++) {
                const int mm = wmm + it * 32;
                Ws[nb][wkkb + 0][mm] = nwv[it].x; Ws[nb][wkkb + 1][mm] = nwv[it].y;
                Ws[nb][wkkb + 2][mm] = nwv[it].z; Ws[nb][wkkb + 3][mm] = nwv[it].w;
            }
            store_x_frag(Xs[nb], nxv, k0 + 16, tid);
            __syncthreads();
            buf = nb;
        }
    }
#pragma unroll
    for (int ih = 0; ih < 2; ih++)
#pragma unroll
        for (int i = 0; i < 4; i++) {
            const int co = co0 + ih * 64 + ty * 4 + i;   // 0..511
            const float bias = b1[co];
#pragma unroll
            for (int jh = 0; jh < 2; jh++) {
                const int l = jh * 32 + tx * 4;
                float4 v = make_float4(acc[ih*4+i][jh*4+0] + bias,
                                       acc[ih*4+i][jh*4+1] + bias,
                                       acc[ih*4+i][jh*4+2] + bias,
                                       acc[ih*4+i][jh*4+3] + bias);
                *(float4*)&Cg[(size_t)co * LTXT + l] = v;
            }
        }
}

// ============================================================================
// K5b: k=3 inception branch. out channels [512,1024). 3-tap shifted GEMM.
// w3 layout [512][2048][3] (tap innermost). tile 128x64, BK=16, 128 thr.
// Double-buffered smem: next tile's loads are issued BEFORE the compute block
// (stores drain into the idle buffer), single barrier per K-step.
// blockIdx.z: 0 -> gamma (wg), 1 -> beta (wb)
// ============================================================================
__device__ __forceinline__ void k5c3_fill(
        float Ws[48][128], float Xs[16][64],
        const float* __restrict__ w3, const float* __restrict__ T,
        const float* __restrict__ IC, int co0, int k0, int tid) {
    // weight tile: each row segment is 48 contiguous floats (16 ci x 3 taps)
#pragma unroll
    for (int it = 0; it < 16; it++) {
        const int mm = (tid >> 4) + it * 8;   // 0..127
        const int c  = tid & 15;
        if (c < 12) {
            float4 wv = *(const float4*)&w3[(size_t)(co0 + mm) * (CIMG * 3)
                                            + (size_t)k0 * 3 + c * 4];
            Ws[c * 4 + 0][mm] = wv.x; Ws[c * 4 + 1][mm] = wv.y;
            Ws[c * 4 + 2][mm] = wv.z; Ws[c * 4 + 3][mm] = wv.w;
        }
    }
    load_x_tile(Xs, T, IC, k0, tid);
}

__global__ __launch_bounds__(128) void k5_conv3(
        const float* __restrict__ text,
        const float* __restrict__ wg, const float* __restrict__ bg,
        const float* __restrict__ wb, const float* __restrict__ bb) {
    __shared__ float Ws[2][48][128];   // [kk*3+dk][co]
    __shared__ float Xs[2][16][64];
    const int n     = blockIdx.y;
    const int co0   = blockIdx.x * 128;   // 0..384 (within 512 conv3 channels)
    const int which = blockIdx.z;
    const float* w3 = which ? wb : wg;
    const float* b3 = which ? bb : bg;
    const float* T  = text + (size_t)n * LTXT * CTXT;
    const float* IC = g_img_cat + (size_t)n * CO * LTXT;
    float* Cg = (which ? g_beta : g_gamma) + (size_t)n * CO * LTXT;
    const int tid = threadIdx.x;
    const int tx = tid & 7, ty = tid >> 3;

    float acc[8][8];
#pragma unroll
    for (int i = 0; i < 8; i++)
#pragma unroll
        for (int j = 0; j < 8; j++) acc[i][j] = 0.f;

    // prologue: fill buffer 0
    k5c3_fill(Ws[0], Xs[0], w3, T, IC, co0, 0, tid);
    __syncthreads();

    int buf = 0;
    for (int k0 = 0; k0 < CIMG; k0 += 16) {
        const bool has_next = (k0 + 16) < CIMG;
        if (has_next) {
            // fill the idle buffer before computing; no barrier needed here
            k5c3_fill(Ws[buf ^ 1], Xs[buf ^ 1], w3, T, IC, co0, k0 + 16, tid);
        }
#pragma unroll
        for (int kk = 0; kk < 16; kk++) {
            // shifted window covering all 3 taps for both n-frag groups
            float bA[6], bB[6];
#pragma unroll
            for (int u = 0; u < 6; u++) {
                const int xi = tx * 4 + u - 1;          // -1..32
                bA[u] = (xi >= 0) ? Xs[buf][kk][xi] : 0.f;
                const int xj = 32 + tx * 4 + u - 1;     // 31..64
                bB[u] = (xj < 64) ? Xs[buf][kk][xj] : 0.f;
            }
#pragma unroll
            for (int dk = 0; dk < 3; dk++) {
                float4 a0 = *(const float4*)&Ws[buf][kk * 3 + dk][ty * 4];
                float4 a1 = *(const float4*)&Ws[buf][kk * 3 + dk][64 + ty * 4];
                float a[8] = {a0.x, a0.y, a0.z, a0.w, a1.x, a1.y, a1.z, a1.w};
                float b[8] = {bA[dk], bA[dk+1], bA[dk+2], bA[dk+3],
                              bB[dk], bB[dk+1], bB[dk+2], bB[dk+3]};
#pragma unroll
                for (int i = 0; i < 8; i++)
#pragma unroll
                    for (int j = 0; j < 8; j++)
                        acc[i][j] = fmaf(a[i], b[j], acc[i][j]);
            }
        }
        if (has_next) {
            __syncthreads();
            buf ^= 1;
        }
    }
#pragma unroll
    for (int ih = 0; ih < 2; ih++)
#pragma unroll
        for (int i = 0; i < 4; i++) {
            const int cow = co0 + ih * 64 + ty * 4 + i;  // 0..511 within branch
            const int ch  = 512 + cow;                   // global channel
            const float bias = b3[cow];
#pragma unroll
            for (int jh = 0; jh < 2; jh++) {
                const int l = jh * 32 + tx * 4;
                float4 v = make_float4(acc[ih*4+i][jh*4+0] + bias,
                                       acc[ih*4+i][jh*4+1] + bias,
                                       acc[ih*4+i][jh*4+2] + bias,
                                       acc[ih*4+i][jh*4+3] + bias);
                *(float4*)&Cg[(size_t)ch * LTXT + l] = v;
            }
        }
}

// ============================================================================
// K6: out = gamma * img_cat + beta   (elementwise, float4)
// ============================================================================
__global__ __launch_bounds__(256) void k6_epilogue(float* __restrict__ out) {
    const size_t i = ((size_t)blockIdx.x * 256 + threadIdx.x) * 4;
    float4 g = *(const float4*)&g_gamma[i];
    float4 b = *(const float4*)&g_beta[i];
    float4 c = *(const float4*)&g_img_cat[i];
    float4 r = make_float4(fmaf(g.x, c.x, b.x), fmaf(g.y, c.y, b.y),
                           fmaf(g.z, c.z, b.z), fmaf(g.w, c.w, b.w));
    *(float4*)&out[i] = r;
}

// ============================================================================
extern "C" void kernel_launch(void* const* d_in, const int* in_sizes, int n_in,
                              void* d_out, int out_size) {
    (void)in_sizes; (void)n_in; (void)out_size;
    const float* img  = (const float*)d_in[0];
    const float* text = (const float*)d_in[1];
    const float* wimg = (const float*)d_in[2];
    const float* wg1  = (const float*)d_in[3];
    const float* bg1  = (const float*)d_in[4];
    const float* wg3  = (const float*)d_in[5];
    const float* bg3  = (const float*)d_in[6];
    const float* wb1  = (const float*)d_in[7];
    const float* bb1  = (const float*)d_in[8];
    const float* wb3  = (const float*)d_in[9];
    const float* bb3  = (const float*)d_in[10];

    float* out  = (float*)d_out;                         // [64][1024][64]
    float* attn = out + (size_t)NB * CO * LTXT;          // [64][64][256]

    k1_img_embed<<<dim3(HW / 128, CO / 128, NB), 256>>>(img, wimg);
    k2_logits  <<<dim3(HW / 64, NB), 256>>>(text, attn);
    k3_softmax <<<NB * LTXT, 256>>>(attn);
    k4_img_cat <<<dim3(CO / 64, NB), 256>>>(attn);
    k5_conv1   <<<dim3(4, NB, 2), 128>>>(text, wg1, bg1, wb1, bb1);
    k5_conv3   <<<dim3(4, NB, 2), 128>>>(text, wg3, bg3, wb3, bb3);
    k6_epilogue<<<(NB * CO * LTXT) / (256 * 4), 256>>>(out);
}